// round 1
// baseline (speedup 1.0000x reference)
#include <cuda_runtime.h>
#include <cstdint>

#define DDIM   512
#define KCODES 512
#define TM     128
#define TNC    128
#define TK     16
#define PAD    132   // smem row pitch (floats): keeps float4 alignment, limits conflicts

static __device__ float g_zn[131072];
static __device__ float g_pn[KCODES];

// ---------------------------------------------------------------------------
// Row squared-norm: one warp per row (512 floats = 4 float4 per lane)
// dst: 0 -> g_zn, 1 -> g_pn
// ---------------------------------------------------------------------------
__global__ void row_norm_kernel(const float* __restrict__ x, int rows, int dst)
{
    int row = blockIdx.x * (blockDim.x >> 5) + (threadIdx.x >> 5);
    if (row >= rows) return;
    int lane = threadIdx.x & 31;
    const float4* xr = reinterpret_cast<const float4*>(x) + (size_t)row * (DDIM / 4);
    float s = 0.f;
#pragma unroll
    for (int i = 0; i < (DDIM / 4) / 32; ++i) {
        float4 v = xr[lane + 32 * i];
        s += v.x * v.x + v.y * v.y + v.z * v.z + v.w * v.w;
    }
#pragma unroll
    for (int o = 16; o; o >>= 1) s += __shfl_xor_sync(0xffffffffu, s, o);
    if (lane == 0) {
        if (dst) g_pn[row] = s;
        else     g_zn[row] = s;
    }
}

// float -> order-preserving unsigned (total order incl. negatives)
__device__ __forceinline__ unsigned fenc(float f)
{
    unsigned b = __float_as_uint(f);
    return (b & 0x80000000u) ? ~b : (b | 0x80000000u);
}

// ---------------------------------------------------------------------------
// Fused: z@P^T (fp32 SGEMM, 128x128 tile, 8x8 micro-tile) -> per-row argmin
// over all 512 codes (4 column-tiles in-CTA) -> gather + blend epilogue.
// ---------------------------------------------------------------------------
__global__ __launch_bounds__(256, 2) void vq_fused_kernel(
    const float* __restrict__ z, const float* __restrict__ P,
    float* __restrict__ zhat, float* __restrict__ ztil, float* __restrict__ idxf)
{
    __shared__ float As[TK][PAD];   // z tile,  k-major: As[k][row]
    __shared__ float Bs[TK][PAD];   // P tile,  k-major: Bs[k][col]
    __shared__ unsigned long long best[TM];
    __shared__ float s_zn[TM];
    __shared__ float s_pn[TNC];

    const int tid  = threadIdx.x;
    const int row0 = blockIdx.x * TM;

    if (tid < TM) { best[tid] = ~0ull; s_zn[tid] = g_zn[row0 + tid]; }

    const int ty = tid >> 4;   // 0..15 : row group (8 rows)
    const int tx = tid & 15;   // 0..15 : col group (8 cols)

    for (int ct = 0; ct < 4; ++ct) {
        const int col0 = ct * TNC;
        __syncthreads();                       // prior-iter readers of s_pn done
        if (tid < TNC) s_pn[tid] = g_pn[col0 + tid];

        float acc[8][8];
#pragma unroll
        for (int i = 0; i < 8; ++i)
#pragma unroll
            for (int j = 0; j < 8; ++j) acc[i][j] = 0.f;

        for (int kk = 0; kk < DDIM; kk += TK) {
            __syncthreads();
            // stage 128x16 tiles of z and P (transposed into k-major smem)
#pragma unroll
            for (int h = 0; h < 2; ++h) {
                int s = tid + h * 256;         // 0..511 slots (128 rows x 4 f4)
                int r = s >> 2;
                int q = s & 3;
                float4 va = *reinterpret_cast<const float4*>(
                    &z[(size_t)(row0 + r) * DDIM + kk + q * 4]);
                As[q * 4 + 0][r] = va.x; As[q * 4 + 1][r] = va.y;
                As[q * 4 + 2][r] = va.z; As[q * 4 + 3][r] = va.w;
                float4 vb = *reinterpret_cast<const float4*>(
                    &P[(size_t)(col0 + r) * DDIM + kk + q * 4]);
                Bs[q * 4 + 0][r] = vb.x; Bs[q * 4 + 1][r] = vb.y;
                Bs[q * 4 + 2][r] = vb.z; Bs[q * 4 + 3][r] = vb.w;
            }
            __syncthreads();
#pragma unroll
            for (int k = 0; k < TK; ++k) {
                float4 a0 = *reinterpret_cast<const float4*>(&As[k][ty * 8]);
                float4 a1 = *reinterpret_cast<const float4*>(&As[k][ty * 8 + 4]);
                float4 b0 = *reinterpret_cast<const float4*>(&Bs[k][tx * 8]);
                float4 b1 = *reinterpret_cast<const float4*>(&Bs[k][tx * 8 + 4]);
                float a[8] = {a0.x, a0.y, a0.z, a0.w, a1.x, a1.y, a1.z, a1.w};
                float b[8] = {b0.x, b0.y, b0.z, b0.w, b1.x, b1.y, b1.z, b1.w};
#pragma unroll
                for (int i = 0; i < 8; ++i)
#pragma unroll
                    for (int j = 0; j < 8; ++j)
                        acc[i][j] += a[i] * b[j];
            }
        }

        // score this 128x128 tile: dist = fl(fl(zn+pn) - 2*dot)  (matches ref rounding)
#pragma unroll
        for (int i = 0; i < 8; ++i) {
            const int r = ty * 8 + i;
            const float zn = s_zn[r];
            unsigned long long mk = ~0ull;
#pragma unroll
            for (int j = 0; j < 8; ++j) {
                const int c = tx * 8 + j;
                float t    = __fadd_rn(zn, s_pn[c]);
                float dist = __fadd_rn(t, -2.0f * acc[i][j]);
                unsigned long long key =
                    ((unsigned long long)fenc(dist) << 32) | (unsigned)(col0 + c);
                mk = (key < mk) ? key : mk;
            }
            atomicMin(&best[r], mk);
        }
    }
    __syncthreads();

    if (tid < TM)
        idxf[row0 + tid] = (float)(unsigned)(best[tid] & 0xffffffffull);

    // epilogue: gather codeword, blend, write (coalesced float4)
    for (int i = tid; i < TM * (DDIM / 4); i += 256) {
        int r  = i >> 7;          // row within tile (DDIM/4 == 128)
        int c4 = i & 127;
        int code = (int)(unsigned)(best[r] & 0xffffffffull);
        size_t go = (size_t)(row0 + r) * DDIM + (size_t)c4 * 4;
        float4 zv = *reinterpret_cast<const float4*>(&z[go]);
        float4 pv = *reinterpret_cast<const float4*>(&P[(size_t)code * DDIM + (size_t)c4 * 4]);
        float4 hv;
        hv.x = __fadd_rn(__fmul_rn(0.7f, zv.x), __fmul_rn(0.3f, pv.x));
        hv.y = __fadd_rn(__fmul_rn(0.7f, zv.y), __fmul_rn(0.3f, pv.y));
        hv.z = __fadd_rn(__fmul_rn(0.7f, zv.z), __fmul_rn(0.3f, pv.z));
        hv.w = __fadd_rn(__fmul_rn(0.7f, zv.w), __fmul_rn(0.3f, pv.w));
        *reinterpret_cast<float4*>(&ztil[go]) = pv;
        *reinterpret_cast<float4*>(&zhat[go]) = hv;
    }
}

extern "C" void kernel_launch(void* const* d_in, const int* in_sizes, int n_in,
                              void* d_out, int out_size)
{
    const float* z = (const float*)d_in[0];
    const float* P = (const float*)d_in[1];
    int N = in_sizes[0] / DDIM;      // 131072

    float* out  = (float*)d_out;
    float* zhat = out;
    float* ztil = out + (size_t)N * DDIM;
    float* idxf = out + 2 * (size_t)N * DDIM;

    row_norm_kernel<<<(N + 7) / 8, 256>>>(z, N, 0);
    row_norm_kernel<<<(KCODES + 7) / 8, 256>>>(P, KCODES, 1);
    vq_fused_kernel<<<N / TM, 256>>>(z, P, zhat, ztil, idxf);
}

// round 5
// speedup vs baseline: 2.5320x; 2.5320x over previous
#include <cuda_runtime.h>
#include <cuda_bf16.h>
#include <cstdint>

#define DDIM 512
#define KC   512
#define TMR  128

// smem layout (bytes)
#define OFF_ZS  0         // 128 rows x 1024B bf16, swizzled
#define OFF_PS  131072    // 2 x 32768 P chunk double buffer; reused as cand table
#define OFF_PN  196608    // 512 f32
#define OFF_ZN  198656    // 128 f32
#define SMEM_SZ 199168

typedef unsigned long long ull;

static __device__ __align__(128) __nv_bfloat16 g_pb[KC * DDIM];
static __device__ float g_pn[KC];

__device__ __forceinline__ uint32_t smem_u32(const void* p) {
    uint32_t a;
    asm("{ .reg .u64 t; cvta.to.shared.u64 t, %1; cvt.u32.u64 %0, t; }" : "=r"(a) : "l"(p));
    return a;
}
__device__ __forceinline__ unsigned fenc(float f) {
    unsigned b = __float_as_uint(f);
    return (b & 0x80000000u) ? ~b : (b | 0x80000000u);
}
__device__ __forceinline__ uint32_t bf2(float a, float b) {
    __nv_bfloat162 h = __floats2bfloat162_rn(a, b);
    return *reinterpret_cast<uint32_t*>(&h);
}
__device__ __forceinline__ void ldsm_x4(uint32_t* r, uint32_t addr) {
    asm volatile("ldmatrix.sync.aligned.m8n8.x4.shared.b16 {%0,%1,%2,%3}, [%4];"
        : "=r"(r[0]), "=r"(r[1]), "=r"(r[2]), "=r"(r[3]) : "r"(addr));
}
__device__ __forceinline__ void ldsm_x2(uint32_t& r0, uint32_t& r1, uint32_t addr) {
    asm volatile("ldmatrix.sync.aligned.m8n8.x2.shared.b16 {%0,%1}, [%2];"
        : "=r"(r0), "=r"(r1) : "r"(addr));
}
__device__ __forceinline__ void mma_bf16(float* c, const uint32_t* a, uint32_t b0, uint32_t b1) {
    asm volatile("mma.sync.aligned.m16n8k16.row.col.f32.bf16.bf16.f32 "
        "{%0,%1,%2,%3}, {%4,%5,%6,%7}, {%8,%9}, {%0,%1,%2,%3};"
        : "+f"(c[0]), "+f"(c[1]), "+f"(c[2]), "+f"(c[3])
        : "r"(a[0]), "r"(a[1]), "r"(a[2]), "r"(a[3]), "r"(b0), "r"(b1));
}
#define CP_COMMIT() asm volatile("cp.async.commit_group;" ::: "memory")

// ---------------- P prep: bf16 copy + norms ----------------
__global__ void p_prep(const float* __restrict__ P) {
    int row = blockIdx.x * 8 + (threadIdx.x >> 5);
    if (row >= KC) return;
    int lane = threadIdx.x & 31;
    const float4* pr = reinterpret_cast<const float4*>(P) + (size_t)row * 128;
    uint2* pb = reinterpret_cast<uint2*>(g_pb) + (size_t)row * 128;
    float s = 0.f;
#pragma unroll
    for (int i = 0; i < 4; ++i) {
        float4 v = pr[lane + 32 * i];
        s += v.x * v.x + v.y * v.y + v.z * v.z + v.w * v.w;
        uint2 o; o.x = bf2(v.x, v.y); o.y = bf2(v.z, v.w);
        pb[lane + 32 * i] = o;
    }
#pragma unroll
    for (int o = 16; o; o >>= 1) s += __shfl_xor_sync(0xffffffffu, s, o);
    if (lane == 0) g_pn[row] = s;
}

// ---------------- P chunk loader (cp.async, swizzled) ----------------
__device__ __forceinline__ void load_chunk(uint32_t sb, int i, int tid) {
    const int ct = i >> 3, kc = i & 7, buf = i & 1;
    const int n = tid;                     // 0..255 codes of this col-tile
    const __nv_bfloat16* src = g_pb + (size_t)(ct * 256 + n) * DDIM + kc * 64;
    uint32_t dst = sb + OFF_PS + buf * 32768 + n * 128;
#pragma unroll
    for (int c = 0; c < 8; ++c) {
        uint32_t d = dst + (uint32_t)((c ^ (n & 7)) << 4);
        asm volatile("cp.async.cg.shared.global [%0], [%1], 16;"
                     :: "r"(d), "l"((const void*)(src + c * 8)) : "memory");
    }
}

// ---------------- fused main kernel ----------------
__global__ void __launch_bounds__(256, 1) vq_main(
    const float* __restrict__ z, const float* __restrict__ Pf,
    float* __restrict__ zhat, float* __restrict__ ztil, float* __restrict__ idxf)
{
    extern __shared__ char smem[];
    const uint32_t sb = smem_u32(smem);
    const int tid = threadIdx.x, wid = tid >> 5, lane = tid & 31;
    const int row0 = blockIdx.x * TMR;
    const int m0 = (wid & 1) * 64;
    const int n0 = (wid >> 1) * 64;

    float* s_pn = reinterpret_cast<float*>(smem + OFF_PN);
    float* s_zn = reinterpret_cast<float*>(smem + OFF_ZN);

    // prefetch first P chunk early
    load_chunk(sb, 0, tid);
    CP_COMMIT();

    for (int i = tid; i < KC; i += 256) s_pn[i] = g_pn[i];

    // prologue: z -> bf16 smem (swizzled), fused squared norm
    {
        const int r = tid >> 1, half = tid & 1;
        const float4* zr = reinterpret_cast<const float4*>(z)
                         + (size_t)(row0 + r) * 128 + half * 64;
        float s = 0.f;
#pragma unroll 8
        for (int c = 0; c < 32; ++c) {
            float4 v0 = zr[c * 2], v1 = zr[c * 2 + 1];
            s += v0.x * v0.x + v0.y * v0.y + v0.z * v0.z + v0.w * v0.w;
            s += v1.x * v1.x + v1.y * v1.y + v1.z * v1.z + v1.w * v1.w;
            uint4 o;
            o.x = bf2(v0.x, v0.y); o.y = bf2(v0.z, v0.w);
            o.z = bf2(v1.x, v1.y); o.w = bf2(v1.z, v1.w);
            int chunk = (half * 32 + c) ^ (r & 7);
            *reinterpret_cast<uint4*>(smem + OFF_ZS + r * 1024 + chunk * 16) = o;
        }
        s += __shfl_xor_sync(0xffffffffu, s, 1);
        if (half == 0) s_zn[r] = s;
    }

    float acc[4][8][4];
    ull best[8][4];
#pragma unroll
    for (int s = 0; s < 8; ++s)
#pragma unroll
        for (int j = 0; j < 4; ++j) best[s][j] = ~0ull;
#pragma unroll
    for (int mt = 0; mt < 4; ++mt)
#pragma unroll
        for (int nt = 0; nt < 8; ++nt)
#pragma unroll
            for (int e = 0; e < 4; ++e) acc[mt][nt][e] = 0.f;

    // main pipeline: 16 chunks = 2 col-tiles x 8 k-chunks, double-buffered
    for (int i = 0; i < 16; ++i) {
        if (i < 15) { load_chunk(sb, i + 1, tid); CP_COMMIT(); }
        if (i < 15) asm volatile("cp.async.wait_group 1;" ::: "memory");
        else        asm volatile("cp.async.wait_group 0;" ::: "memory");
        __syncthreads();

        const int ct = i >> 3, kcl = i & 7;
        const uint32_t pbase = sb + OFF_PS + (i & 1) * 32768;
#pragma unroll
        for (int kk = 0; kk < 4; ++kk) {
            const int kg = kcl * 64 + kk * 16;
            uint32_t a[4][4];
#pragma unroll
            for (int mt = 0; mt < 4; ++mt) {
                int rg = m0 + mt * 16 + (lane & 15);
                int kq = kg + ((lane >> 4) << 3);
                uint32_t ad = sb + OFF_ZS + rg * 1024
                            + (uint32_t)((((kq >> 3) ^ (rg & 7))) << 4);
                ldsm_x4(a[mt], ad);
            }
#pragma unroll
            for (int nt = 0; nt < 8; ++nt) {
                int nl = n0 + nt * 8 + (lane & 7);
                int kq = kk * 16 + (((lane >> 3) & 1) << 3);
                uint32_t bd = pbase + nl * 128
                            + (uint32_t)((((kq >> 3) ^ (nl & 7))) << 4);
                uint32_t b0, b1;
                ldsm_x2(b0, b1, bd);
#pragma unroll
                for (int mt = 0; mt < 4; ++mt) mma_bf16(acc[mt][nt], a[mt], b0, b1);
            }
        }

        if (kcl == 7) {
            // merge this col-tile's dists into per-lane top-4, then clear acc
            const int ctbase = ct * 256;
#pragma unroll
            for (int mt = 0; mt < 4; ++mt)
#pragma unroll
                for (int half = 0; half < 2; ++half) {
                    const int s = mt * 2 + half;
                    const int rloc = m0 + mt * 16 + half * 8 + (lane >> 2);
                    const float zn = s_zn[rloc];
#pragma unroll
                    for (int nt = 0; nt < 8; ++nt)
#pragma unroll
                        for (int e = 0; e < 2; ++e) {
                            const int col = ctbase + n0 + nt * 8 + (lane & 3) * 2 + e;
                            float d = acc[mt][nt][half * 2 + e];
                            float dist = __fmaf_rn(-2.f, d, zn + s_pn[col]);
                            ull key = ((ull)fenc(dist) << 32) | (unsigned)col;
                            if (key < best[s][3]) {
                                best[s][3] = key;
                                if (best[s][3] < best[s][2]) { ull t = best[s][2]; best[s][2] = best[s][3]; best[s][3] = t; }
                                if (best[s][2] < best[s][1]) { ull t = best[s][1]; best[s][1] = best[s][2]; best[s][2] = t; }
                                if (best[s][1] < best[s][0]) { ull t = best[s][0]; best[s][0] = best[s][1]; best[s][1] = t; }
                            }
                            acc[mt][nt][half * 2 + e] = 0.f;
                        }
                }
        }
        __syncthreads();
    }

    // dump per-lane top-4 into cand table (reuses P buffers)
    ull* tab = reinterpret_cast<ull*>(smem + OFF_PS);
    {
        const int slot = (wid >> 1) * 4 + (lane & 3);
#pragma unroll
        for (int s = 0; s < 8; ++s) {
            const int mt = s >> 1, half = s & 1;
            const int rloc = m0 + mt * 16 + half * 8 + (lane >> 2);
#pragma unroll
            for (int j = 0; j < 4; ++j)
                tab[(rloc * 16 + slot) * 4 + j] = best[s][j];
        }
    }
    __syncthreads();

    // per-row: global top-4 of 64 keys -> exact fp32 rescore -> winner -> outputs
    const float4* z4 = reinterpret_cast<const float4*>(z);
    const float4* P4 = reinterpret_cast<const float4*>(Pf);
    float4* zh4 = reinterpret_cast<float4*>(zhat);
    float4* zt4 = reinterpret_cast<float4*>(ztil);

    for (int rr = 0; rr < 16; ++rr) {
        const int r = wid * 16 + rr;
        float4 za[4];
#pragma unroll
        for (int q = 0; q < 4; ++q)
            za[q] = z4[(size_t)(row0 + r) * 128 + q * 32 + lane];
        const float zn = s_zn[r];

        ull k0_ = tab[r * 64 + lane];
        ull k1_ = tab[r * 64 + 32 + lane];
        ull winkey = ~0ull;
#pragma unroll
        for (int it = 0; it < 4; ++it) {
            ull m = k0_ < k1_ ? k0_ : k1_;
#pragma unroll
            for (int o = 16; o; o >>= 1) {
                ull om = __shfl_xor_sync(0xffffffffu, m, o);
                m = om < m ? om : m;
            }
            const int c = (int)(m & 511ull);
            if (k0_ == m) k0_ = ~0ull;
            if (k1_ == m) k1_ = ~0ull;

            float s_ = 0.f;
#pragma unroll
            for (int q = 0; q < 4; ++q) {
                float4 pb = P4[(size_t)c * 128 + q * 32 + lane];
                s_ = fmaf(za[q].x, pb.x, s_);
                s_ = fmaf(za[q].y, pb.y, s_);
                s_ = fmaf(za[q].z, pb.z, s_);
                s_ = fmaf(za[q].w, pb.w, s_);
            }
#pragma unroll
            for (int o = 16; o; o >>= 1) s_ += __shfl_xor_sync(0xffffffffu, s_, o);
            float t = __fadd_rn(zn, s_pn[c]);
            float dist = __fadd_rn(t, -2.0f * s_);
            ull key = ((ull)fenc(dist) << 32) | (unsigned)c;
            winkey = key < winkey ? key : winkey;
        }
        const int c = (int)(winkey & 511ull);
#pragma unroll
        for (int q = 0; q < 4; ++q) {
            float4 pv = P4[(size_t)c * 128 + q * 32 + lane];
            size_t go = (size_t)(row0 + r) * 128 + q * 32 + lane;
            float4 hv;
            hv.x = __fadd_rn(__fmul_rn(0.7f, za[q].x), __fmul_rn(0.3f, pv.x));
            hv.y = __fadd_rn(__fmul_rn(0.7f, za[q].y), __fmul_rn(0.3f, pv.y));
            hv.z = __fadd_rn(__fmul_rn(0.7f, za[q].z), __fmul_rn(0.3f, pv.z));
            hv.w = __fadd_rn(__fmul_rn(0.7f, za[q].w), __fmul_rn(0.3f, pv.w));
            zt4[go] = pv;
            zh4[go] = hv;
        }
        if (lane == 0) idxf[row0 + r] = (float)c;
    }
}

extern "C" void kernel_launch(void* const* d_in, const int* in_sizes, int n_in,
                              void* d_out, int out_size)
{
    const float* z = (const float*)d_in[0];
    const float* P = (const float*)d_in[1];
    int N = in_sizes[0] / DDIM;   // 131072

    float* out  = (float*)d_out;
    float* zhat = out;
    float* ztil = out + (size_t)N * DDIM;
    float* idxf = out + 2 * (size_t)N * DDIM;

    cudaFuncSetAttribute(vq_main, cudaFuncAttributeMaxDynamicSharedMemorySize, SMEM_SZ);

    p_prep<<<KC / 8, 256>>>(P);
    vq_main<<<N / TMR, 256, SMEM_SZ>>>(z, P, zhat, ztil, idxf);
}

// round 6
// speedup vs baseline: 2.9651x; 1.1710x over previous
#include <cuda_runtime.h>
#include <cuda_bf16.h>
#include <cstdint>

#define DDIM 512
#define KC   512
#define TMR  128

// smem layout (bytes)
#define OFF_ZS  0         // 128 rows x 1024B bf16, swizzled
#define OFF_PS  131072    // 2 x 32768 P chunk double buffer; reused as 64KB cand table
#define OFF_PN  196608    // 512 f32
#define OFF_ZN  198656    // 128 f32
#define SMEM_SZ 199168

typedef unsigned long long ull;

static __device__ __align__(128) __nv_bfloat16 g_pb[KC * DDIM];
static __device__ float g_pn[KC];

__device__ __forceinline__ uint32_t smem_u32(const void* p) {
    uint32_t a;
    asm("{ .reg .u64 t; cvta.to.shared.u64 t, %1; cvt.u32.u64 %0, t; }" : "=r"(a) : "l"(p));
    return a;
}
__device__ __forceinline__ unsigned fenc(float f) {
    unsigned b = __float_as_uint(f);
    return (b & 0x80000000u) ? ~b : (b | 0x80000000u);
}
__device__ __forceinline__ uint32_t bf2(float a, float b) {
    __nv_bfloat162 h = __floats2bfloat162_rn(a, b);
    return *reinterpret_cast<uint32_t*>(&h);
}
__device__ __forceinline__ void ldsm_x4(uint32_t* r, uint32_t addr) {
    asm volatile("ldmatrix.sync.aligned.m8n8.x4.shared.b16 {%0,%1,%2,%3}, [%4];"
        : "=r"(r[0]), "=r"(r[1]), "=r"(r[2]), "=r"(r[3]) : "r"(addr));
}
__device__ __forceinline__ void mma_bf16(float* c, const uint32_t* a, uint32_t b0, uint32_t b1) {
    asm volatile("mma.sync.aligned.m16n8k16.row.col.f32.bf16.bf16.f32 "
        "{%0,%1,%2,%3}, {%4,%5,%6,%7}, {%8,%9}, {%0,%1,%2,%3};"
        : "+f"(c[0]), "+f"(c[1]), "+f"(c[2]), "+f"(c[3])
        : "r"(a[0]), "r"(a[1]), "r"(a[2]), "r"(a[3]), "r"(b0), "r"(b1));
}
#define CP_COMMIT() asm volatile("cp.async.commit_group;" ::: "memory")

// ---------------- P prep: bf16 copy + norms ----------------
__global__ void p_prep(const float* __restrict__ P) {
    int row = blockIdx.x * 8 + (threadIdx.x >> 5);
    if (row >= KC) return;
    int lane = threadIdx.x & 31;
    const float4* pr = reinterpret_cast<const float4*>(P) + (size_t)row * 128;
    uint2* pb = reinterpret_cast<uint2*>(g_pb) + (size_t)row * 128;
    float s = 0.f;
#pragma unroll
    for (int i = 0; i < 4; ++i) {
        float4 v = pr[lane + 32 * i];
        s += v.x * v.x + v.y * v.y + v.z * v.z + v.w * v.w;
        uint2 o; o.x = bf2(v.x, v.y); o.y = bf2(v.z, v.w);
        pb[lane + 32 * i] = o;
    }
#pragma unroll
    for (int o = 16; o; o >>= 1) s += __shfl_xor_sync(0xffffffffu, s, o);
    if (lane == 0) g_pn[row] = s;
}

// ---------------- P chunk loader (cp.async, swizzled), 512 threads ----------------
__device__ __forceinline__ void load_chunk(uint32_t sb, int i, int tid) {
    const int ct = i >> 3, kc = i & 7, buf = i & 1;
    const int n = tid >> 1, half = tid & 1;       // 256 codes, 2 threads/code
    const __nv_bfloat16* src = g_pb + (size_t)(ct * 256 + n) * DDIM + kc * 64 + half * 32;
    uint32_t dst = sb + OFF_PS + buf * 32768 + n * 128;
#pragma unroll
    for (int j = 0; j < 4; ++j) {
        int c = half * 4 + j;
        uint32_t d = dst + (uint32_t)((c ^ (n & 7)) << 4);
        asm volatile("cp.async.cg.shared.global [%0], [%1], 16;"
                     :: "r"(d), "l"((const void*)(src + j * 8)) : "memory");
    }
}

// ---------------- fused main kernel: 512 threads, 16 warps ----------------
__global__ void __launch_bounds__(512, 1) vq_main(
    const float* __restrict__ z, const float* __restrict__ Pf,
    float* __restrict__ zhat, float* __restrict__ ztil, float* __restrict__ idxf)
{
    extern __shared__ char smem[];
    const uint32_t sb = smem_u32(smem);
    const int tid = threadIdx.x, wid = tid >> 5, lane = tid & 31;
    const int row0 = blockIdx.x * TMR;
    const int m0 = (wid & 3) * 32;        // 4 m-warps x 32 rows
    const int n0 = (wid >> 2) * 64;       // 4 n-warps x 64 cols

    float* s_pn = reinterpret_cast<float*>(smem + OFF_PN);
    float* s_zn = reinterpret_cast<float*>(smem + OFF_ZN);

    // prefetch first P chunk early
    load_chunk(sb, 0, tid);
    CP_COMMIT();

    for (int i = tid; i < KC; i += 512) s_pn[i] = g_pn[i];

    // prologue: z -> bf16 smem (swizzled), fused squared norm (4 threads/row)
    {
        const int r = tid >> 2, q = tid & 3;
        const float4* zr = reinterpret_cast<const float4*>(z)
                         + (size_t)(row0 + r) * 128 + q * 32;
        float s = 0.f;
#pragma unroll 4
        for (int c = 0; c < 16; ++c) {
            float4 v0 = zr[c * 2], v1 = zr[c * 2 + 1];
            s += v0.x * v0.x + v0.y * v0.y + v0.z * v0.z + v0.w * v0.w;
            s += v1.x * v1.x + v1.y * v1.y + v1.z * v1.z + v1.w * v1.w;
            uint4 o;
            o.x = bf2(v0.x, v0.y); o.y = bf2(v0.z, v0.w);
            o.z = bf2(v1.x, v1.y); o.w = bf2(v1.z, v1.w);
            int chunk = (q * 16 + c) ^ (r & 7);
            *reinterpret_cast<uint4*>(smem + OFF_ZS + r * 1024 + chunk * 16) = o;
        }
        s += __shfl_xor_sync(0xffffffffu, s, 1);
        s += __shfl_xor_sync(0xffffffffu, s, 2);
        if (q == 0) s_zn[r] = s;
    }

    float acc[2][8][4];
    ull best[4][4];
#pragma unroll
    for (int s = 0; s < 4; ++s)
#pragma unroll
        for (int j = 0; j < 4; ++j) best[s][j] = ~0ull;
#pragma unroll
    for (int mt = 0; mt < 2; ++mt)
#pragma unroll
        for (int nt = 0; nt < 8; ++nt)
#pragma unroll
            for (int e = 0; e < 4; ++e) acc[mt][nt][e] = 0.f;

    // main pipeline: 16 chunks = 2 col-tiles x 8 k-chunks, double-buffered
    for (int i = 0; i < 16; ++i) {
        if (i < 15) { load_chunk(sb, i + 1, tid); CP_COMMIT(); }
        if (i < 15) asm volatile("cp.async.wait_group 1;" ::: "memory");
        else        asm volatile("cp.async.wait_group 0;" ::: "memory");
        __syncthreads();

        const int ct = i >> 3, kcl = i & 7;
        const uint32_t pbase = sb + OFF_PS + (i & 1) * 32768;
#pragma unroll
        for (int kk = 0; kk < 4; ++kk) {
            const int kg = kcl * 64 + kk * 16;
            uint32_t a[2][4];
#pragma unroll
            for (int mt = 0; mt < 2; ++mt) {
                int rg = m0 + mt * 16 + (lane & 15);
                int kq = kg + ((lane >> 4) << 3);
                uint32_t ad = sb + OFF_ZS + rg * 1024
                            + (uint32_t)((((kq >> 3) ^ (rg & 7))) << 4);
                ldsm_x4(a[mt], ad);
            }
#pragma unroll
            for (int ntp = 0; ntp < 4; ++ntp) {
                // x4: lanes 0-15 -> n8 tile (2*ntp), lanes 16-31 -> tile (2*ntp+1)
                int nl = n0 + ntp * 16 + ((lane >> 4) << 3) + (lane & 7);
                int kq8 = kk * 2 + ((lane >> 3) & 1);
                uint32_t bd = pbase + nl * 128
                            + (uint32_t)(((kq8 ^ (nl & 7))) << 4);
                uint32_t rb[4];
                ldsm_x4(rb, bd);
#pragma unroll
                for (int mt = 0; mt < 2; ++mt) {
                    mma_bf16(acc[mt][ntp * 2],     a[mt], rb[0], rb[1]);
                    mma_bf16(acc[mt][ntp * 2 + 1], a[mt], rb[2], rb[3]);
                }
            }
        }

        if (kcl == 7) {
            // merge this col-tile's dists into per-lane top-4, then clear acc
            const int ctbase = ct * 256;
#pragma unroll
            for (int mt = 0; mt < 2; ++mt)
#pragma unroll
                for (int half = 0; half < 2; ++half) {
                    const int s = mt * 2 + half;
                    const int rloc = m0 + mt * 16 + half * 8 + (lane >> 2);
                    const float zn = s_zn[rloc];
#pragma unroll
                    for (int nt = 0; nt < 8; ++nt)
#pragma unroll
                        for (int e = 0; e < 2; ++e) {
                            const int col = ctbase + n0 + nt * 8 + (lane & 3) * 2 + e;
                            float d = acc[mt][nt][half * 2 + e];
                            float dist = __fmaf_rn(-2.f, d, zn + s_pn[col]);
                            ull key = ((ull)fenc(dist) << 32) | (unsigned)col;
                            if (key < best[s][3]) {
                                best[s][3] = key;
                                if (best[s][3] < best[s][2]) { ull t = best[s][2]; best[s][2] = best[s][3]; best[s][3] = t; }
                                if (best[s][2] < best[s][1]) { ull t = best[s][1]; best[s][1] = best[s][2]; best[s][2] = t; }
                                if (best[s][1] < best[s][0]) { ull t = best[s][0]; best[s][0] = best[s][1]; best[s][1] = t; }
                            }
                            acc[mt][nt][half * 2 + e] = 0.f;
                        }
                }
        }
        __syncthreads();
    }

    // dump per-lane top-4 into cand table (reuses P buffers): 128 rows x 16 slots x 4
    ull* tab = reinterpret_cast<ull*>(smem + OFF_PS);
    {
        const int slot = (wid >> 2) * 4 + (lane & 3);
#pragma unroll
        for (int s = 0; s < 4; ++s) {
            const int mt = s >> 1, half = s & 1;
            const int rloc = m0 + mt * 16 + half * 8 + (lane >> 2);
#pragma unroll
            for (int j = 0; j < 4; ++j)
                tab[(rloc * 16 + slot) * 4 + j] = best[s][j];
        }
    }
    __syncthreads();

    // per-row: global top-4 of 64 keys -> exact fp32 rescore -> winner -> outputs
    const float4* z4 = reinterpret_cast<const float4*>(z);
    const float4* P4 = reinterpret_cast<const float4*>(Pf);
    float4* zh4 = reinterpret_cast<float4*>(zhat);
    float4* zt4 = reinterpret_cast<float4*>(ztil);

    for (int rr = 0; rr < 8; ++rr) {
        const int r = wid * 8 + rr;
        float4 za[4];
#pragma unroll
        for (int q = 0; q < 4; ++q)
            za[q] = z4[(size_t)(row0 + r) * 128 + q * 32 + lane];
        const float zn = s_zn[r];

        ull k0_ = tab[r * 64 + lane];
        ull k1_ = tab[r * 64 + 32 + lane];
        ull winkey = ~0ull;
#pragma unroll
        for (int it = 0; it < 4; ++it) {
            ull m = k0_ < k1_ ? k0_ : k1_;
#pragma unroll
            for (int o = 16; o; o >>= 1) {
                ull om = __shfl_xor_sync(0xffffffffu, m, o);
                m = om < m ? om : m;
            }
            const int c = (int)(m & 511ull);
            if (k0_ == m) k0_ = ~0ull;
            if (k1_ == m) k1_ = ~0ull;

            float s_ = 0.f;
#pragma unroll
            for (int q = 0; q < 4; ++q) {
                float4 pb = P4[(size_t)c * 128 + q * 32 + lane];
                s_ = fmaf(za[q].x, pb.x, s_);
                s_ = fmaf(za[q].y, pb.y, s_);
                s_ = fmaf(za[q].z, pb.z, s_);
                s_ = fmaf(za[q].w, pb.w, s_);
            }
#pragma unroll
            for (int o = 16; o; o >>= 1) s_ += __shfl_xor_sync(0xffffffffu, s_, o);
            float t = __fadd_rn(zn, s_pn[c]);
            float dist = __fadd_rn(t, -2.0f * s_);
            ull key = ((ull)fenc(dist) << 32) | (unsigned)c;
            winkey = key < winkey ? key : winkey;
        }
        const int c = (int)(winkey & 511ull);
#pragma unroll
        for (int q = 0; q < 4; ++q) {
            float4 pv = P4[(size_t)c * 128 + q * 32 + lane];
            size_t go = (size_t)(row0 + r) * 128 + q * 32 + lane;
            float4 hv;
            hv.x = __fadd_rn(__fmul_rn(0.7f, za[q].x), __fmul_rn(0.3f, pv.x));
            hv.y = __fadd_rn(__fmul_rn(0.7f, za[q].y), __fmul_rn(0.3f, pv.y));
            hv.z = __fadd_rn(__fmul_rn(0.7f, za[q].z), __fmul_rn(0.3f, pv.z));
            hv.w = __fadd_rn(__fmul_rn(0.7f, za[q].w), __fmul_rn(0.3f, pv.w));
            zt4[go] = pv;
            zh4[go] = hv;
        }
        if (lane == 0) idxf[row0 + r] = (float)c;
    }
}

extern "C" void kernel_launch(void* const* d_in, const int* in_sizes, int n_in,
                              void* d_out, int out_size)
{
    const float* z = (const float*)d_in[0];
    const float* P = (const float*)d_in[1];
    int N = in_sizes[0] / DDIM;   // 131072

    float* out  = (float*)d_out;
    float* zhat = out;
    float* ztil = out + (size_t)N * DDIM;
    float* idxf = out + 2 * (size_t)N * DDIM;

    cudaFuncSetAttribute(vq_main, cudaFuncAttributeMaxDynamicSharedMemorySize, SMEM_SZ);

    p_prep<<<KC / 8, 256>>>(P);
    vq_main<<<N / TMR, 512, SMEM_SZ>>>(z, P, zhat, ztil, idxf);
}